// round 4
// baseline (speedup 1.0000x reference)
#include <cuda_runtime.h>
#include <math.h>

#define IN_F   512
#define HID    256
#define BATCH  1024

// Precomputed edge masks: bit set = "normal edge" (take x), clear = no_edge.
__device__ unsigned int g_mask0[HID * (IN_F / 32)];  // [256][16]
__device__ unsigned int g_mask1[IN_F * (HID / 32)];  // [512][8]

// ---------------------------------------------------------------------------
// Kernel 1: build bitmasks from (logits, u). One thread per edge, ballot-pack.
// ---------------------------------------------------------------------------
__global__ __launch_bounds__(256)
void mask_kernel(const float* __restrict__ logits0, const float* __restrict__ u0,
                 const float* __restrict__ logits1, const float* __restrict__ u1)
{
    int g = blockIdx.x * blockDim.x + threadIdx.x;   // 0 .. 262143
    const float* L;
    const float* U;
    unsigned int* M;
    int idx;
    if (g < HID * IN_F) { L = logits0; U = u0; M = g_mask0; idx = g; }
    else                { L = logits1; U = u1; M = g_mask1; idx = g - HID * IN_F; }

    float2 l = reinterpret_cast<const float2*>(L)[idx];
    float2 u = reinterpret_cast<const float2*>(U)[idx];

    const float LO = 1e-10f;
    const float HI = 1.0f - 1e-10f;
    float ca = fminf(fmaxf(u.x, LO), HI);
    float cb = fminf(fmaxf(u.y, LO), HI);

    bool pred;
    if (l.x == l.y) {
        pred = cb > ca;                       // gumbel monotone in clipped u
    } else {
        float g0 = -logf(-logf(ca));
        float g1 = -logf(-logf(cb));
        pred = (l.y + g1) > (l.x + g0);
    }

    unsigned bal = __ballot_sync(0xFFFFFFFFu, pred);
    if ((threadIdx.x & 31) == 0) M[idx >> 5] = bal;
}

// ---------------------------------------------------------------------------
// Kernel 2: fused two-layer evaluation, one block per batch row.
//   Layer 0: counting sort of x (uniform -> linear buckets, ~1/bucket).
//   Layer 1: counting sort of h with LOG buckets (hbits>>19, exp+4 mantissa
//            bits) -- matches the min-of-uniforms distribution.
//   Probes: 8-wide batched first-hit search (2x LDS.128 + 8 independent
//            mask LDGs per batch), same-bucket rescan keeps results exact.
// ---------------------------------------------------------------------------
__global__ __launch_bounds__(256)
void row_kernel(const float* __restrict__ x, float* __restrict__ out)
{
    __shared__ unsigned cnt[IN_F];    // counts, then exclusive offsets
    __shared__ unsigned skey[IN_F];   // sorted keys: (bucket<<9)|idx
    __shared__ float    sval[IN_F];   // exact x row
    __shared__ float    shv[HID];     // exact h row
    __shared__ unsigned wsum[8];

    const int b    = blockIdx.x;
    const int t    = threadIdx.x;     // 0..255
    const int lane = t & 31;
    const int w    = t >> 5;

    // ================= layer 0: counting sort of x (512 linear buckets) ====
    cnt[t] = 0; cnt[t + 256] = 0;
    float v0 = x[b * IN_F + t];
    float v1 = x[b * IN_F + t + 256];
    sval[t] = v0; sval[t + 256] = v1;
    __syncthreads();

    int b0 = min((int)(v0 * 512.0f), 511);   // exact pow2 scaling -> monotone
    int b1 = min((int)(v1 * 512.0f), 511);
    unsigned r0 = atomicAdd(&cnt[b0], 1u);
    unsigned r1 = atomicAdd(&cnt[b1], 1u);
    __syncthreads();

    // exclusive scan of 512 counts: thread t owns buckets 2t, 2t+1
    unsigned c0 = cnt[2 * t], c1 = cnt[2 * t + 1];
    unsigned s  = c0 + c1, sc = s;
#pragma unroll
    for (int d = 1; d < 32; d <<= 1) {
        unsigned o = __shfl_up_sync(0xFFFFFFFFu, sc, d);
        if (lane >= d) sc += o;
    }
    if (lane == 31) wsum[w] = sc;
    __syncthreads();
    unsigned wexcl = 0;
#pragma unroll
    for (int i = 0; i < 8; i++) if (i < w) wexcl += wsum[i];
    unsigned excl = wexcl + (sc - s);
    cnt[2 * t]     = excl;
    cnt[2 * t + 1] = excl + c0;
    __syncthreads();

    skey[cnt[b0] + r0] = ((unsigned)b0 << 9) | (unsigned)t;
    skey[cnt[b1] + r1] = ((unsigned)b1 << 9) | (unsigned)(t + 256);
    __syncthreads();

    // ---- layer 0 probe (batched 8-wide): thread t owns hidden unit t ----
    const unsigned* __restrict__ m0 = g_mask0 + t * (IN_F / 32);
    float h = 1.0f;
    {
        int found = -1;
        for (int base = 0; base < IN_F && found < 0; base += 8) {
            uint4 a = ((const uint4*)skey)[base >> 2];
            uint4 c = ((const uint4*)skey)[(base >> 2) + 1];
            unsigned ks[8] = {a.x, a.y, a.z, a.w, c.x, c.y, c.z, c.w};
            unsigned hit = 0;
#pragma unroll
            for (int q = 0; q < 8; q++) {
                unsigned i = ks[q] & 511u;
                hit |= ((m0[i >> 5] >> (i & 31)) & 1u) << q;  // 8 indep LDGs
            }
            if (hit) {
                int q0 = __ffs(hit) - 1;
                found = base + q0;
                unsigned qb = ks[q0] >> 9;
                h = sval[ks[q0] & 511u];
#pragma unroll
                for (int q = 0; q < 8; q++)      // exact-min over tie bucket
                    if (q > q0 && ((hit >> q) & 1u) && (ks[q] >> 9) == qb)
                        h = fminf(h, sval[ks[q] & 511u]);
                if ((ks[7] >> 9) == qb) {        // bucket spills past batch
                    for (int k2 = base + 8; k2 < IN_F; k2++) {
                        unsigned key2 = skey[k2];
                        if ((key2 >> 9) != qb) break;
                        unsigned i2 = key2 & 511u;
                        if ((m0[i2 >> 5] >> (i2 & 31)) & 1u) h = fminf(h, sval[i2]);
                    }
                }
            }
        }
    }
    __syncthreads();                         // probes done before smem reuse

    // ====== layer 1: counting sort of h with log buckets (descending) ======
    shv[t] = h;
    cnt[t] = 0;
    __syncthreads();

    // bucket = clamp((hbits>>19) - 1792, 0, 255): exp + top-4 mantissa bits,
    // monotone in h for h >= 0; h <= 1.0 -> max bucket 240.
    unsigned hb  = __float_as_uint(h);
    int bkt = min(max((int)(hb >> 19) - 1792, 0), 255);
    int bd  = 255 - bkt;                     // descending order
    unsigned rr = atomicAdd(&cnt[bd], 1u);
    __syncthreads();

    unsigned c = cnt[t], scn = c;
#pragma unroll
    for (int d = 1; d < 32; d <<= 1) {
        unsigned o = __shfl_up_sync(0xFFFFFFFFu, scn, d);
        if (lane >= d) scn += o;
    }
    if (lane == 31) wsum[w] = scn;
    __syncthreads();
    unsigned wex = 0;
#pragma unroll
    for (int i = 0; i < 8; i++) if (i < w) wex += wsum[i];
    cnt[t] = wex + scn - c;                  // exclusive offset of bucket t
    __syncthreads();

    skey[cnt[bd] + rr] = ((unsigned)bd << 9) | (unsigned)t;
    __syncthreads();

    // ---- layer 1 probe (batched 8-wide): outputs o = t and t + 256 ----
#pragma unroll
    for (int half = 0; half < 2; half++) {
        int o = t + half * 256;
        const unsigned* __restrict__ m1 = g_mask1 + o * (HID / 32);
        float r = 0.0f;
        int found = -1;
        for (int base = 0; base < HID && found < 0; base += 8) {
            uint4 a = ((const uint4*)skey)[base >> 2];
            uint4 c4 = ((const uint4*)skey)[(base >> 2) + 1];
            unsigned ks[8] = {a.x, a.y, a.z, a.w, c4.x, c4.y, c4.z, c4.w};
            unsigned hit = 0;
#pragma unroll
            for (int q = 0; q < 8; q++) {
                unsigned j = ks[q] & 511u;
                hit |= ((m1[j >> 5] >> (j & 31)) & 1u) << q;
            }
            if (hit) {
                int q0 = __ffs(hit) - 1;
                found = base + q0;
                unsigned qb = ks[q0] >> 9;
                r = shv[ks[q0] & 511u];
#pragma unroll
                for (int q = 0; q < 8; q++)      // exact-max over tie bucket
                    if (q > q0 && ((hit >> q) & 1u) && (ks[q] >> 9) == qb)
                        r = fmaxf(r, shv[ks[q] & 511u]);
                if ((ks[7] >> 9) == qb) {
                    for (int k2 = base + 8; k2 < HID; k2++) {
                        unsigned key2 = skey[k2];
                        if ((key2 >> 9) != qb) break;
                        unsigned j2 = key2 & 511u;
                        if ((m1[j2 >> 5] >> (j2 & 31)) & 1u) r = fmaxf(r, shv[j2]);
                    }
                }
            }
        }
        out[b * IN_F + o] = r;
    }
}

// ---------------------------------------------------------------------------
// kernel_launch: graph-capturable, allocation-free.
// Inputs: x, logits0, u0, logits1, u1. Output: float32 [1024,512].
// ---------------------------------------------------------------------------
extern "C" void kernel_launch(void* const* d_in, const int* in_sizes, int n_in,
                              void* d_out, int out_size)
{
    const float* x       = (const float*)d_in[0];
    const float* logits0 = (const float*)d_in[1];
    const float* u0      = (const float*)d_in[2];
    const float* logits1 = (const float*)d_in[3];
    const float* u1      = (const float*)d_in[4];
    float* out = (float*)d_out;

    mask_kernel<<<(HID * IN_F * 2) / 256, 256>>>(logits0, u0, logits1, u1);
    row_kernel<<<BATCH, 256>>>(x, out);
}